// round 2
// baseline (speedup 1.0000x reference)
#include <cuda_runtime.h>
#include <cuda_bf16.h>
#include <cstdint>

// ---------------- problem constants (fixed by setup_inputs) ----------------
#define NPTS   20000
#define NDST   5000
#define KNB    32
#define NPAD   20480          // padded to 512*20*2
#define NPAIR  10240          // NPAD/2
#define FPS_THREADS 512
#define PAIRS_PER_THREAD 20   // 512*20 = 10240 pairs

// output layout (float32, concatenated in reference return order)
#define OFF_COORD 0
#define OFF_FEAT  15000
#define OFF_ESRC  655000
#define OFF_EDST  815000
#define OFF_DEG   975000
#define OFF_BATCH 980000

// rounding-variant switches (iterate empirically if rel_err mismatches)
#define BALL_DOT_FMA 1        // 1: fma-chain dot (Eigen/cublas style), 0: mul+add

static __device__ float g_ssrc[NPTS];
static __device__ int   g_sel[NDST];
static __device__ int   g_nbr[NDST * KNB];
static __device__ int   g_deg[NDST];

typedef unsigned long long u64;

__device__ __forceinline__ u64 f2_add(u64 a, u64 b) {
    u64 r; asm("add.rn.f32x2 %0, %1, %2;" : "=l"(r) : "l"(a), "l"(b)); return r;
}
__device__ __forceinline__ u64 f2_mul(u64 a, u64 b) {
    u64 r; asm("mul.rn.f32x2 %0, %1, %2;" : "=l"(r) : "l"(a), "l"(b)); return r;
}
__device__ __forceinline__ u64 f2_pack(float lo, float hi) {
    u64 r; asm("mov.b64 %0, {%1, %2};" : "=l"(r) : "f"(lo), "f"(hi)); return r;
}
__device__ __forceinline__ float2 f2_unpack(u64 a) {
    float2 v; asm("mov.b64 {%0, %1}, %2;" : "=f"(v.x), "=f"(v.y) : "l"(a)); return v;
}

// reference-order squared distance: ((dx*dx + dy*dy) + dz*dz), no fma
__device__ __forceinline__ float d2_ref(float x, float y, float z,
                                        float cx, float cy, float cz) {
    float dx = __fsub_rn(x, cx), dy = __fsub_rn(y, cy), dz = __fsub_rn(z, cz);
    return __fadd_rn(__fadd_rn(__fmul_rn(dx, dx), __fmul_rn(dy, dy)),
                     __fmul_rn(dz, dz));
}

// ---------------- sum of squares per src point ----------------
__global__ void ssrc_kernel(const float* __restrict__ coord) {
    int j = blockIdx.x * blockDim.x + threadIdx.x;
    if (j < NPTS) {
        float x = coord[3 * j], y = coord[3 * j + 1], z = coord[3 * j + 2];
        g_ssrc[j] = __fadd_rn(__fadd_rn(__fmul_rn(x, x), __fmul_rn(y, y)),
                              __fmul_rn(z, z));
    }
}

// ---------------- farthest point sampling (single persistent block) --------
__global__ __launch_bounds__(FPS_THREADS, 1)
void fps_kernel(const float* __restrict__ coord, float* __restrict__ out) {
    extern __shared__ float sm[];
    float* sXX = sm;           // [NPAD] x coords, pair-contiguous
    float* sYY = sm + NPAD;    // [NPAD] y coords
    __shared__ float sWarp[16];
    __shared__ float sBM;
    __shared__ int   sSel;
    __shared__ float sCx, sCy, sCz;

    const int t = threadIdx.x;

    float mind[2 * PAIRS_PER_THREAD];
    u64   zp[PAIRS_PER_THREAD];

    const float c0x = coord[0], c0y = coord[1], c0z = coord[2];
    float tmax = -1e30f;

#pragma unroll
    for (int k = 0; k < PAIRS_PER_THREAD; k++) {
        int pr = t + k * FPS_THREADS;
        int i0 = 2 * pr, i1 = 2 * pr + 1;
        float x0, y0, z0, x1, y1, z1, m0, m1;
        if (i0 < NPTS) {
            x0 = coord[3 * i0]; y0 = coord[3 * i0 + 1]; z0 = coord[3 * i0 + 2];
            m0 = d2_ref(x0, y0, z0, c0x, c0y, c0z);
        } else { x0 = y0 = z0 = 1e18f; m0 = -1.0f; }
        if (i1 < NPTS) {
            x1 = coord[3 * i1]; y1 = coord[3 * i1 + 1]; z1 = coord[3 * i1 + 2];
            m1 = d2_ref(x1, y1, z1, c0x, c0y, c0z);
        } else { x1 = y1 = z1 = 1e18f; m1 = -1.0f; }
        sXX[i0] = x0; sXX[i1] = x1;
        sYY[i0] = y0; sYY[i1] = y1;
        zp[k] = f2_pack(z0, z1);
        mind[2 * k] = m0; mind[2 * k + 1] = m1;
        tmax = fmaxf(tmax, fmaxf(m0, m1));
    }
    if (t == 0) {
        g_sel[0] = 0;
        out[OFF_COORD + 0] = c0x; out[OFF_COORD + 1] = c0y; out[OFF_COORD + 2] = c0z;
    }
    __syncthreads();

    for (int i = 1; i < NDST; i++) {
        // --- block max of mind (value only) ---
        float v = tmax;
#pragma unroll
        for (int off = 16; off; off >>= 1)
            v = fmaxf(v, __shfl_xor_sync(0xffffffffu, v, off));
        if ((t & 31) == 0) sWarp[t >> 5] = v;
        __syncthreads();
        if (t < 16) {
            float w = sWarp[t];
#pragma unroll
            for (int off = 8; off; off >>= 1)
                w = fmaxf(w, __shfl_xor_sync(0x0000ffffu, w, off));
            if (t == 0) { sBM = w; sSel = 0x7fffffff; }
        }
        __syncthreads();

        // --- resolve argmax index (first/smallest index on ties) ---
        const float bm = sBM;
        if (tmax == bm) {
#pragma unroll
            for (int k = 0; k < PAIRS_PER_THREAD; k++) {
                int pr = t + k * FPS_THREADS;
                if (mind[2 * k] == bm)     atomicMin(&sSel, 2 * pr);
                if (mind[2 * k + 1] == bm) atomicMin(&sSel, 2 * pr + 1);
            }
        }
        __syncthreads();

        // --- owning thread publishes the new center ---
        const int sel = sSel;
        const int pr = sel >> 1;
        if (t == (pr & (FPS_THREADS - 1))) {
            const int kk = pr >> 9;  // pr / 512
            float cz = 0.0f;
#pragma unroll
            for (int k = 0; k < PAIRS_PER_THREAD; k++)
                if (k == kk) {
                    float2 zz = f2_unpack(zp[k]);
                    cz = (sel & 1) ? zz.y : zz.x;
                }
            float cx = sXX[sel], cy = sYY[sel];
            sCx = cx; sCy = cy; sCz = cz;
            g_sel[i] = sel;
            out[OFF_COORD + 3 * i]     = cx;
            out[OFF_COORD + 3 * i + 1] = cy;
            out[OFF_COORD + 3 * i + 2] = cz;
        }
        __syncthreads();

        // --- update min distances (packed f32x2; exact per-element rounding) ---
        const u64 ncx = f2_pack(-sCx, -sCx);
        const u64 ncy = f2_pack(-sCy, -sCy);
        const u64 ncz = f2_pack(-sCz, -sCz);
        float tA = -1e30f, tB = -1e30f;
#pragma unroll
        for (int k = 0; k < PAIRS_PER_THREAD; k++) {
            int pr2 = t + k * FPS_THREADS;
            u64 xx = *reinterpret_cast<const u64*>(&sXX[2 * pr2]);
            u64 yy = *reinterpret_cast<const u64*>(&sYY[2 * pr2]);
            u64 dx = f2_add(xx, ncx);
            u64 dy = f2_add(yy, ncy);
            u64 dz = f2_add(zp[k], ncz);
            u64 d2 = f2_add(f2_add(f2_mul(dx, dx), f2_mul(dy, dy)), f2_mul(dz, dz));
            float2 d = f2_unpack(d2);
            mind[2 * k]     = fminf(mind[2 * k], d.x);
            mind[2 * k + 1] = fminf(mind[2 * k + 1], d.y);
            tA = fmaxf(tA, mind[2 * k]);
            tB = fmaxf(tB, mind[2 * k + 1]);
        }
        tmax = fmaxf(tA, tB);
    }
}

// ---------------- ball query: one warp per dst, ordered append -------------
__global__ void ball_kernel(const float* __restrict__ coord,
                            const int* __restrict__ batch,
                            float* __restrict__ out) {
    __shared__ int sN[4][KNB];
    const int warp = threadIdx.x >> 5;
    const int lane = threadIdx.x & 31;
    const int d = blockIdx.x * 4 + warp;
    if (d >= NDST) return;

    const float R2 = (float)(0.08 * 0.08);
    const int sel = g_sel[d];
    const float cx = coord[3 * sel], cy = coord[3 * sel + 1], cz = coord[3 * sel + 2];
    const float sd = g_ssrc[sel];

    int cnt = 0;
    for (int j0 = 0; j0 < NPTS; j0 += 32) {
        const int j = j0 + lane;   // NPTS % 32 == 0, no tail
        float xj = coord[3 * j], yj = coord[3 * j + 1], zj = coord[3 * j + 2];
        float sj = g_ssrc[j];
#if BALL_DOT_FMA
        float dot = __fmaf_rn(cz, zj, __fmaf_rn(cy, yj, __fmul_rn(cx, xj)));
#else
        float dot = __fadd_rn(__fadd_rn(__fmul_rn(cx, xj), __fmul_rn(cy, yj)),
                              __fmul_rn(cz, zj));
#endif
        float d2 = __fsub_rn(__fadd_rn(sd, sj), __fmul_rn(2.0f, dot));
        bool w = (d2 <= R2);
        unsigned bal = __ballot_sync(0xffffffffu, w);
        int pos = cnt + __popc(bal & ((1u << lane) - 1u));
        if (w && pos < KNB) sN[warp][pos] = j;
        cnt += __popc(bal);
        if (cnt >= KNB) break;
    }
    __syncwarp();

    const int deg = min(cnt, KNB);
    const int base = d * KNB;
    int nb = (lane < deg) ? sN[warp][lane] : -1;
    g_nbr[base + lane] = nb;
    out[OFF_ESRC + base + lane] = (float)nb;
    out[OFF_EDST + base + lane] = (lane < deg) ? (float)d : -1.0f;
    if (lane == 0) {
        g_deg[d] = deg;
        out[OFF_DEG + d] = (float)deg;
        out[OFF_BATCH + d] = (float)batch[sel];
    }
}

// ---------------- feature scatter-mean: one block (128 thr) per dst --------
__global__ void feat_kernel(const float* __restrict__ feat,
                            float* __restrict__ out) {
    __shared__ int sNbr[KNB];
    __shared__ int sDeg;
    const int d = blockIdx.x;
    const int tid = threadIdx.x;
    if (tid < KNB) sNbr[tid] = g_nbr[d * KNB + tid];
    if (tid == 0)  sDeg = g_deg[d];
    __syncthreads();
    const int dg = sDeg;
    float acc = 0.0f;
    for (int k = 0; k < dg; k++)
        acc = __fadd_rn(acc, feat[(size_t)sNbr[k] * 128 + tid]);
    out[OFF_FEAT + (size_t)d * 128 + tid] = acc / (float)max(dg, 1);
}

// ---------------- launch ----------------
extern "C" void kernel_launch(void* const* d_in, const int* in_sizes, int n_in,
                              void* d_out, int out_size) {
    const float* coord = (const float*)d_in[0];
    const float* feat  = (const float*)d_in[1];
    const int*   batch = (const int*)d_in[2];
    float* out = (float*)d_out;

    const int smem = 2 * NPAD * sizeof(float);  // 163840 B
    cudaFuncSetAttribute(fps_kernel, cudaFuncAttributeMaxDynamicSharedMemorySize, smem);

    ssrc_kernel<<<(NPTS + 255) / 256, 256>>>(coord);
    fps_kernel<<<1, FPS_THREADS, smem>>>(coord, out);
    ball_kernel<<<(NDST + 3) / 4, 128>>>(coord, batch, out);
    feat_kernel<<<NDST, 128>>>(feat, out);
}

// round 3
// speedup vs baseline: 1.0709x; 1.0709x over previous
#include <cuda_runtime.h>
#include <cuda_bf16.h>
#include <cstdint>

// ---------------- problem constants (fixed by setup_inputs) ----------------
#define NPTS   20000
#define NDST   5000
#define KNB    32

// FPS multi-block config
#define FPS_B  8
#define FPS_T  256
#define PPT    5                              // pairs per thread (10 points)
#define PTS_PER_BLOCK (FPS_T * PPT * 2)       // 2560
#define PAIRS_PER_BLOCK (FPS_T * PPT)         // 1280

// output layout (float32, concatenated in reference return order)
#define OFF_COORD 0
#define OFF_FEAT  15000
#define OFF_ESRC  655000
#define OFF_EDST  815000
#define OFF_DEG   975000
#define OFF_BATCH 980000

static __device__ float g_ssrc[NPTS];
static __device__ int   g_sel[NDST];
static __device__ int   g_nbr[NDST * KNB];
static __device__ int   g_deg[NDST];
static __device__ unsigned long long g_slot[2][FPS_B];

typedef unsigned long long u64;

__device__ __forceinline__ u64 f2_add(u64 a, u64 b) {
    u64 r; asm("add.rn.f32x2 %0, %1, %2;" : "=l"(r) : "l"(a), "l"(b)); return r;
}
__device__ __forceinline__ u64 f2_mul(u64 a, u64 b) {
    u64 r; asm("mul.rn.f32x2 %0, %1, %2;" : "=l"(r) : "l"(a), "l"(b)); return r;
}
__device__ __forceinline__ u64 f2_pack(float lo, float hi) {
    u64 r; asm("mov.b64 %0, {%1, %2};" : "=l"(r) : "f"(lo), "f"(hi)); return r;
}
__device__ __forceinline__ float2 f2_unpack(u64 a) {
    float2 v; asm("mov.b64 {%0, %1}, %2;" : "=f"(v.x), "=f"(v.y) : "l"(a)); return v;
}
__device__ __forceinline__ u64 ld_acq(const u64* p) {
    u64 v; asm volatile("ld.acquire.gpu.u64 %0, [%1];" : "=l"(v) : "l"(p)); return v;
}
__device__ __forceinline__ void st_rel(u64* p, u64 v) {
    asm volatile("st.release.gpu.u64 [%0], %1;" :: "l"(p), "l"(v));
}

// reference-order squared distance: ((dx*dx + dy*dy) + dz*dz), no fma
__device__ __forceinline__ float d2_ref(float x, float y, float z,
                                        float cx, float cy, float cz) {
    float dx = __fsub_rn(x, cx), dy = __fsub_rn(y, cy), dz = __fsub_rn(z, cz);
    return __fadd_rn(__fadd_rn(__fmul_rn(dx, dx), __fmul_rn(dy, dy)),
                     __fmul_rn(dz, dz));
}

// ---------------- sum of squares per src point + slot reset ----------------
__global__ void ssrc_kernel(const float* __restrict__ coord) {
    if (blockIdx.x == 0 && threadIdx.x < 2 * FPS_B)
        ((u64*)g_slot)[threadIdx.x] = 0ull;
    int j = blockIdx.x * blockDim.x + threadIdx.x;
    if (j < NPTS) {
        float x = coord[3 * j], y = coord[3 * j + 1], z = coord[3 * j + 2];
        g_ssrc[j] = __fadd_rn(__fadd_rn(__fmul_rn(x, x), __fmul_rn(y, y)),
                              __fmul_rn(z, z));
    }
}

__device__ __forceinline__ u64 warp_max_u64(u64 v) {
#pragma unroll
    for (int off = 16; off; off >>= 1) {
        u64 o = __shfl_xor_sync(0xffffffffu, v, off);
        v = (o > v) ? o : v;
    }
    return v;
}

// ---------------- farthest point sampling: 8 persistent blocks -------------
__global__ __launch_bounds__(FPS_T, 1)
void fps_kernel(const float* __restrict__ coord, float* __restrict__ out) {
    __shared__ float sXX[PTS_PER_BLOCK];   // x coords, pair-contiguous
    __shared__ float sYY[PTS_PER_BLOCK];   // y coords, pair-contiguous
    __shared__ u64 sBest;
    __shared__ int sSelSh;

    const int t = threadIdx.x;
    const int b = blockIdx.x;
    const int gbase = b * PTS_PER_BLOCK;   // first global point index of block

    float mind[2 * PPT];
    u64   zp[PPT];

    if (t == 0) sBest = 0ull;

    const float c0x = coord[0], c0y = coord[1], c0z = coord[2];
    float tmax = -1e30f;

#pragma unroll
    for (int k = 0; k < PPT; k++) {
        int p  = t + k * FPS_T;            // block-local pair
        int i0 = gbase + 2 * p;            // global indices
        int i1 = i0 + 1;
        float x0, y0, z0, x1, y1, z1, m0, m1;
        if (i0 < NPTS) {
            x0 = coord[3 * i0]; y0 = coord[3 * i0 + 1]; z0 = coord[3 * i0 + 2];
            m0 = d2_ref(x0, y0, z0, c0x, c0y, c0z);
        } else { x0 = y0 = z0 = 1e18f; m0 = -1.0f; }
        if (i1 < NPTS) {
            x1 = coord[3 * i1]; y1 = coord[3 * i1 + 1]; z1 = coord[3 * i1 + 2];
            m1 = d2_ref(x1, y1, z1, c0x, c0y, c0z);
        } else { x1 = y1 = z1 = 1e18f; m1 = -1.0f; }
        sXX[2 * p] = x0; sXX[2 * p + 1] = x1;
        sYY[2 * p] = y0; sYY[2 * p + 1] = y1;
        zp[k] = f2_pack(z0, z1);
        mind[2 * k] = m0; mind[2 * k + 1] = m1;
        tmax = fmaxf(tmax, fmaxf(m0, m1));
    }

    // per-thread first-index of the max
    int bidx = 0x7FFF;
#pragma unroll
    for (int k = 0; k < PPT; k++) {
        int g = gbase + 2 * (t + k * FPS_T);
        if (mind[2 * k] == tmax && g < bidx)           bidx = g;
        if (mind[2 * k + 1] == tmax && (g + 1) < bidx) bidx = g + 1;
    }

    if (b == 0 && t == 0) {
        g_sel[0] = 0;
        out[OFF_COORD + 0] = c0x; out[OFF_COORD + 1] = c0y; out[OFF_COORD + 2] = c0z;
    }
    __syncthreads();

    for (int i = 1; i < NDST; i++) {
        // --- local packed (value, first-index) reduce ---
        u64 e = ((u64)__float_as_uint(fmaxf(tmax, 0.0f)) << 32) |
                (u64)(0x7FFF - bidx);
        e = warp_max_u64(e);
        if ((t & 31) == 0) atomicMax(&sBest, e);
        __syncthreads();

        // --- publish, poll all 8 blocks, pick global winner ---
        if (t == 0) {
            u64 pub = sBest | ((u64)i << 15);
            sBest = 0ull;
            st_rel(&g_slot[i & 1][b], pub);
        }
        u64 ge = 0ull;
        if (t < FPS_B) {
            const u64* slot = &g_slot[i & 1][t];
            do { ge = ld_acq(slot); } while (((ge >> 15) & 0x1FFFu) != (unsigned)i);
        }
        if (t < 32) {
#pragma unroll
            for (int off = 4; off; off >>= 1) {
                u64 o = __shfl_xor_sync(0xffffffffu, ge, off);
                ge = (o > ge) ? o : ge;
            }
            if (t == 0) sSelSh = 0x7FFF - (int)(ge & 0x7FFFu);
        }
        __syncthreads();

        const int sel = sSelSh;
        const float cx = __ldg(coord + 3 * sel);
        const float cy = __ldg(coord + 3 * sel + 1);
        const float cz = __ldg(coord + 3 * sel + 2);
        if (b == 0 && t == 0) {
            g_sel[i] = sel;
            out[OFF_COORD + 3 * i]     = cx;
            out[OFF_COORD + 3 * i + 1] = cy;
            out[OFF_COORD + 3 * i + 2] = cz;
        }

        // --- update min distances (packed f32x2; exact per-element rounding) ---
        const u64 ncx = f2_pack(-cx, -cx);
        const u64 ncy = f2_pack(-cy, -cy);
        const u64 ncz = f2_pack(-cz, -cz);
        float tA = -1e30f, tB = -1e30f;
#pragma unroll
        for (int k = 0; k < PPT; k++) {
            int p = t + k * FPS_T;
            u64 xx = *reinterpret_cast<const u64*>(&sXX[2 * p]);
            u64 yy = *reinterpret_cast<const u64*>(&sYY[2 * p]);
            u64 dx = f2_add(xx, ncx);
            u64 dy = f2_add(yy, ncy);
            u64 dz = f2_add(zp[k], ncz);
            u64 d2 = f2_add(f2_add(f2_mul(dx, dx), f2_mul(dy, dy)), f2_mul(dz, dz));
            float2 d = f2_unpack(d2);
            mind[2 * k]     = fminf(mind[2 * k], d.x);
            mind[2 * k + 1] = fminf(mind[2 * k + 1], d.y);
            tA = fmaxf(tA, mind[2 * k]);
            tB = fmaxf(tB, mind[2 * k + 1]);
        }
        tmax = fmaxf(tA, tB);

        // per-thread first-index of new max
        bidx = 0x7FFF;
#pragma unroll
        for (int k = 0; k < PPT; k++) {
            int g = gbase + 2 * (t + k * FPS_T);
            if (mind[2 * k] == tmax && g < bidx)           bidx = g;
            if (mind[2 * k + 1] == tmax && (g + 1) < bidx) bidx = g + 1;
        }
    }
}

// ---------------- ball query: one warp per dst, ordered append -------------
__global__ void ball_kernel(const float* __restrict__ coord,
                            const int* __restrict__ batch,
                            float* __restrict__ out) {
    __shared__ int sN[4][KNB];
    const int warp = threadIdx.x >> 5;
    const int lane = threadIdx.x & 31;
    const int d = blockIdx.x * 4 + warp;
    if (d >= NDST) return;

    const float R2 = (float)(0.08 * 0.08);
    const int sel = g_sel[d];
    const float cx = coord[3 * sel], cy = coord[3 * sel + 1], cz = coord[3 * sel + 2];
    const float sd = g_ssrc[sel];

    int cnt = 0;
    for (int j0 = 0; j0 < NPTS; j0 += 32) {
        const int j = j0 + lane;   // NPTS % 32 == 0, no tail
        float xj = coord[3 * j], yj = coord[3 * j + 1], zj = coord[3 * j + 2];
        float sj = g_ssrc[j];
        float dot = __fmaf_rn(cz, zj, __fmaf_rn(cy, yj, __fmul_rn(cx, xj)));
        float d2 = __fsub_rn(__fadd_rn(sd, sj), __fmul_rn(2.0f, dot));
        bool w = (d2 <= R2);
        unsigned bal = __ballot_sync(0xffffffffu, w);
        int pos = cnt + __popc(bal & ((1u << lane) - 1u));
        if (w && pos < KNB) sN[warp][pos] = j;
        cnt += __popc(bal);
        if (cnt >= KNB) break;
    }
    __syncwarp();

    const int deg = min(cnt, KNB);
    const int base = d * KNB;
    int nb = (lane < deg) ? sN[warp][lane] : -1;
    g_nbr[base + lane] = nb;
    out[OFF_ESRC + base + lane] = (float)nb;
    out[OFF_EDST + base + lane] = (lane < deg) ? (float)d : -1.0f;
    if (lane == 0) {
        g_deg[d] = deg;
        out[OFF_DEG + d] = (float)deg;
        out[OFF_BATCH + d] = (float)batch[sel];
    }
}

// ---------------- feature scatter-mean: one block (128 thr) per dst --------
__global__ void feat_kernel(const float* __restrict__ feat,
                            float* __restrict__ out) {
    __shared__ int sNbr[KNB];
    __shared__ int sDeg;
    const int d = blockIdx.x;
    const int tid = threadIdx.x;
    if (tid < KNB) sNbr[tid] = g_nbr[d * KNB + tid];
    if (tid == 0)  sDeg = g_deg[d];
    __syncthreads();
    const int dg = sDeg;
    float acc = 0.0f;
    for (int k = 0; k < dg; k++)
        acc = __fadd_rn(acc, feat[(size_t)sNbr[k] * 128 + tid]);
    out[OFF_FEAT + (size_t)d * 128 + tid] = acc / (float)max(dg, 1);
}

// ---------------- launch ----------------
extern "C" void kernel_launch(void* const* d_in, const int* in_sizes, int n_in,
                              void* d_out, int out_size) {
    const float* coord = (const float*)d_in[0];
    const float* feat  = (const float*)d_in[1];
    const int*   batch = (const int*)d_in[2];
    float* out = (float*)d_out;

    ssrc_kernel<<<(NPTS + 255) / 256, 256>>>(coord);
    fps_kernel<<<FPS_B, FPS_T>>>(coord, out);
    ball_kernel<<<(NDST + 3) / 4, 128>>>(coord, batch, out);
    feat_kernel<<<NDST, 128>>>(feat, out);
}

// round 4
// speedup vs baseline: 2.0885x; 1.9501x over previous
#include <cuda_runtime.h>
#include <cuda_bf16.h>
#include <cstdint>

// ---------------- problem constants (fixed by setup_inputs) ----------------
#define NPTS   20000
#define NDST   5000
#define KNB    32

// FPS cluster config
#define FPS_B  8
#define FPS_T  256
#define PPT    5                              // pairs per thread (10 points)
#define PTS_PER_BLOCK (FPS_T * PPT * 2)       // 2560

// output layout (float32, concatenated in reference return order)
#define OFF_COORD 0
#define OFF_FEAT  15000
#define OFF_ESRC  655000
#define OFF_EDST  815000
#define OFF_DEG   975000
#define OFF_BATCH 980000

static __device__ float g_ssrc[NPTS];
static __device__ int   g_sel[NDST];
static __device__ int   g_nbr[NDST * KNB];
static __device__ int   g_deg[NDST];

typedef unsigned long long u64;

__device__ __forceinline__ u64 f2_add(u64 a, u64 b) {
    u64 r; asm("add.rn.f32x2 %0, %1, %2;" : "=l"(r) : "l"(a), "l"(b)); return r;
}
__device__ __forceinline__ u64 f2_mul(u64 a, u64 b) {
    u64 r; asm("mul.rn.f32x2 %0, %1, %2;" : "=l"(r) : "l"(a), "l"(b)); return r;
}
__device__ __forceinline__ u64 f2_pack(float lo, float hi) {
    u64 r; asm("mov.b64 %0, {%1, %2};" : "=l"(r) : "f"(lo), "f"(hi)); return r;
}
__device__ __forceinline__ float2 f2_unpack(u64 a) {
    float2 v; asm("mov.b64 {%0, %1}, %2;" : "=f"(v.x), "=f"(v.y) : "l"(a)); return v;
}

// key layout: [63:51] iter tag (13b) | [50:19] value f32 bits (32b) | [14:0] 0x7fff - idx
__device__ __forceinline__ u64 make_key(unsigned iter, unsigned valbits, unsigned idx) {
    return ((u64)iter << 51) | ((u64)valbits << 19) | (u64)(0x7fffu - idx);
}

// reference-order squared distance: ((dx*dx + dy*dy) + dz*dz), no fma
__device__ __forceinline__ float d2_ref(float x, float y, float z,
                                        float cx, float cy, float cz) {
    float dx = __fsub_rn(x, cx), dy = __fsub_rn(y, cy), dz = __fsub_rn(z, cz);
    return __fadd_rn(__fadd_rn(__fmul_rn(dx, dx), __fmul_rn(dy, dy)),
                     __fmul_rn(dz, dz));
}

// ---------------- sum of squares per src point ----------------
__global__ void ssrc_kernel(const float* __restrict__ coord) {
    int j = blockIdx.x * blockDim.x + threadIdx.x;
    if (j < NPTS) {
        float x = coord[3 * j], y = coord[3 * j + 1], z = coord[3 * j + 2];
        g_ssrc[j] = __fadd_rn(__fadd_rn(__fmul_rn(x, x), __fmul_rn(y, y)),
                              __fmul_rn(z, z));
    }
}

// ---------------- farthest point sampling: 8-CTA cluster, DSMEM exchange ---
__global__ __launch_bounds__(FPS_T, 1) __cluster_dims__(FPS_B, 1, 1)
void fps_kernel(const float* __restrict__ coord, float* __restrict__ out) {
    __shared__ float sXX[PTS_PER_BLOCK];   // x coords, pair-contiguous
    __shared__ float sYY[PTS_PER_BLOCK];   // y coords, pair-contiguous
    __shared__ u64 sSlot[2][FPS_B];        // double-buffered peer candidates
    __shared__ u64 sBest;

    const int t = threadIdx.x;
    const int b = blockIdx.x;              // == cluster rank (grid = 1 cluster)
    const int gbase = b * PTS_PER_BLOCK;

    float mind[2 * PPT];
    u64   zp[PPT];

    if (t < 2 * FPS_B) ((u64*)sSlot)[t] = 0ull;   // tag 0 != any iter >= 1
    if (t == 0) sBest = 0ull;

    const float c0x = coord[0], c0y = coord[1], c0z = coord[2];
    float tmax = -1e30f;

#pragma unroll
    for (int k = 0; k < PPT; k++) {
        int p  = t + k * FPS_T;
        int i0 = gbase + 2 * p;
        int i1 = i0 + 1;
        float x0, y0, z0, x1, y1, z1, m0, m1;
        if (i0 < NPTS) {
            x0 = coord[3 * i0]; y0 = coord[3 * i0 + 1]; z0 = coord[3 * i0 + 2];
            m0 = d2_ref(x0, y0, z0, c0x, c0y, c0z);
        } else { x0 = y0 = z0 = 1e18f; m0 = -1.0f; }
        if (i1 < NPTS) {
            x1 = coord[3 * i1]; y1 = coord[3 * i1 + 1]; z1 = coord[3 * i1 + 2];
            m1 = d2_ref(x1, y1, z1, c0x, c0y, c0z);
        } else { x1 = y1 = z1 = 1e18f; m1 = -1.0f; }
        sXX[2 * p] = x0; sXX[2 * p + 1] = x1;
        sYY[2 * p] = y0; sYY[2 * p + 1] = y1;
        zp[k] = f2_pack(z0, z1);
        mind[2 * k] = m0; mind[2 * k + 1] = m1;
        tmax = fmaxf(tmax, fmaxf(m0, m1));
    }

    // per-thread first-index of the max
    int bidx = 0x7FFF;
#pragma unroll
    for (int k = 0; k < PPT; k++) {
        int g = gbase + 2 * (t + k * FPS_T);
        if (mind[2 * k] == tmax && g < bidx)           bidx = g;
        if (mind[2 * k + 1] == tmax && (g + 1) < bidx) bidx = g + 1;
    }

    if (b == 0 && t == 0) {
        g_sel[0] = 0;
        out[OFF_COORD + 0] = c0x; out[OFF_COORD + 1] = c0y; out[OFF_COORD + 2] = c0z;
    }
    __syncthreads();
    // all CTAs' slot-zeroing must be visible before any remote publish lands
    asm volatile("barrier.cluster.arrive.aligned;" ::: "memory");
    asm volatile("barrier.cluster.wait.aligned;" ::: "memory");

    const uint32_t slotBase = (uint32_t)__cvta_generic_to_shared(&sSlot[0][0]);

    for (int i = 1; i < NDST; i++) {
        // --- local reduce: per-warp redux, per-block atomicMax (tag-dominant) ---
        unsigned vb = __float_as_uint(fmaxf(tmax, 0.0f));
        unsigned wm = __reduce_max_sync(0xffffffffu, vb);
        unsigned ci = (vb == wm) ? (unsigned)bidx : 0x7fffu;
        unsigned im = __reduce_min_sync(0xffffffffu, ci);
        if ((t & 31) == 0) atomicMax(&sBest, make_key((unsigned)i, wm, im));
        __syncthreads();

        // --- publish this block's candidate into every CTA's slot[par][b] ---
        const uint32_t par = (uint32_t)(i & 1);
        if (t < FPS_B) {
            u64 pub = sBest;   // tag already embedded; stale values can't win
            uint32_t la = slotBase + (par * FPS_B + (uint32_t)b) * 8u;
            uint32_t ra;
            asm("mapa.shared::cluster.u32 %0, %1, %2;" : "=r"(ra) : "r"(la), "r"((uint32_t)t));
            asm volatile("st.shared::cluster.u64 [%0], %1;" :: "r"(ra), "l"(pub) : "memory");
        }

        // --- poll local slots; pick global winner ---
        u64 best = 0ull;
#pragma unroll
        for (int r = 0; r < FPS_B; r++) {
            uint32_t la = slotBase + (par * FPS_B + (uint32_t)r) * 8u;
            u64 k;
            do {
                asm volatile("ld.volatile.shared.u64 %0, [%1];" : "=l"(k) : "r"(la));
            } while ((unsigned)(k >> 51) != (unsigned)i);
            best = (k > best) ? k : best;
        }
        const int sel = 0x7FFF - (int)(best & 0x7FFFu);

        // --- center coords (L1 mostly hot: no per-iter cluster.sync flush) ---
        const float cx = __ldg(coord + 3 * sel);
        const float cy = __ldg(coord + 3 * sel + 1);
        const float cz = __ldg(coord + 3 * sel + 2);
        if (b == 0 && t == 0) {
            g_sel[i] = sel;
            out[OFF_COORD + 3 * i]     = cx;
            out[OFF_COORD + 3 * i + 1] = cy;
            out[OFF_COORD + 3 * i + 2] = cz;
        }

        // --- update min distances (packed f32x2; exact per-element rounding) ---
        const u64 ncx = f2_pack(-cx, -cx);
        const u64 ncy = f2_pack(-cy, -cy);
        const u64 ncz = f2_pack(-cz, -cz);
        float tA = -1e30f, tB = -1e30f;
#pragma unroll
        for (int k = 0; k < PPT; k++) {
            int p = t + k * FPS_T;
            u64 xx = *reinterpret_cast<const u64*>(&sXX[2 * p]);
            u64 yy = *reinterpret_cast<const u64*>(&sYY[2 * p]);
            u64 dx = f2_add(xx, ncx);
            u64 dy = f2_add(yy, ncy);
            u64 dz = f2_add(zp[k], ncz);
            u64 d2 = f2_add(f2_add(f2_mul(dx, dx), f2_mul(dy, dy)), f2_mul(dz, dz));
            float2 d = f2_unpack(d2);
            mind[2 * k]     = fminf(mind[2 * k], d.x);
            mind[2 * k + 1] = fminf(mind[2 * k + 1], d.y);
            tA = fmaxf(tA, mind[2 * k]);
            tB = fmaxf(tB, mind[2 * k + 1]);
        }
        tmax = fmaxf(tA, tB);

        // per-thread first-index of new max
        bidx = 0x7FFF;
#pragma unroll
        for (int k = 0; k < PPT; k++) {
            int g = gbase + 2 * (t + k * FPS_T);
            if (mind[2 * k] == tmax && g < bidx)           bidx = g;
            if (mind[2 * k + 1] == tmax && (g + 1) < bidx) bidx = g + 1;
        }
    }

    // keep cluster resident until all remote traffic has been consumed
    asm volatile("barrier.cluster.arrive.aligned;" ::: "memory");
    asm volatile("barrier.cluster.wait.aligned;" ::: "memory");
}

// ---------------- ball query: one warp per dst, ordered append -------------
__global__ void ball_kernel(const float* __restrict__ coord,
                            const int* __restrict__ batch,
                            float* __restrict__ out) {
    __shared__ int sN[4][KNB];
    const int warp = threadIdx.x >> 5;
    const int lane = threadIdx.x & 31;
    const int d = blockIdx.x * 4 + warp;
    if (d >= NDST) return;

    const float R2 = (float)(0.08 * 0.08);
    const int sel = g_sel[d];
    const float cx = coord[3 * sel], cy = coord[3 * sel + 1], cz = coord[3 * sel + 2];
    const float sd = g_ssrc[sel];

    int cnt = 0;
    for (int j0 = 0; j0 < NPTS; j0 += 32) {
        const int j = j0 + lane;   // NPTS % 32 == 0, no tail
        float xj = coord[3 * j], yj = coord[3 * j + 1], zj = coord[3 * j + 2];
        float sj = g_ssrc[j];
        float dot = __fmaf_rn(cz, zj, __fmaf_rn(cy, yj, __fmul_rn(cx, xj)));
        float d2 = __fsub_rn(__fadd_rn(sd, sj), __fmul_rn(2.0f, dot));
        bool w = (d2 <= R2);
        unsigned bal = __ballot_sync(0xffffffffu, w);
        int pos = cnt + __popc(bal & ((1u << lane) - 1u));
        if (w && pos < KNB) sN[warp][pos] = j;
        cnt += __popc(bal);
        if (cnt >= KNB) break;
    }
    __syncwarp();

    const int deg = min(cnt, KNB);
    const int base = d * KNB;
    int nb = (lane < deg) ? sN[warp][lane] : -1;
    g_nbr[base + lane] = nb;
    out[OFF_ESRC + base + lane] = (float)nb;
    out[OFF_EDST + base + lane] = (lane < deg) ? (float)d : -1.0f;
    if (lane == 0) {
        g_deg[d] = deg;
        out[OFF_DEG + d] = (float)deg;
        out[OFF_BATCH + d] = (float)batch[sel];
    }
}

// ---------------- feature scatter-mean: one block (128 thr) per dst --------
__global__ void feat_kernel(const float* __restrict__ feat,
                            float* __restrict__ out) {
    __shared__ int sNbr[KNB];
    __shared__ int sDeg;
    const int d = blockIdx.x;
    const int tid = threadIdx.x;
    if (tid < KNB) sNbr[tid] = g_nbr[d * KNB + tid];
    if (tid == 0)  sDeg = g_deg[d];
    __syncthreads();
    const int dg = sDeg;
    float acc = 0.0f;
    for (int k = 0; k < dg; k++)
        acc = __fadd_rn(acc, feat[(size_t)sNbr[k] * 128 + tid]);
    out[OFF_FEAT + (size_t)d * 128 + tid] = acc / (float)max(dg, 1);
}

// ---------------- launch ----------------
extern "C" void kernel_launch(void* const* d_in, const int* in_sizes, int n_in,
                              void* d_out, int out_size) {
    const float* coord = (const float*)d_in[0];
    const float* feat  = (const float*)d_in[1];
    const int*   batch = (const int*)d_in[2];
    float* out = (float*)d_out;

    ssrc_kernel<<<(NPTS + 255) / 256, 256>>>(coord);
    fps_kernel<<<FPS_B, FPS_T>>>(coord, out);
    ball_kernel<<<(NDST + 3) / 4, 128>>>(coord, batch, out);
    feat_kernel<<<NDST, 128>>>(feat, out);
}

// round 5
// speedup vs baseline: 2.3148x; 1.1084x over previous
#include <cuda_runtime.h>
#include <cuda_bf16.h>
#include <cstdint>

// ---------------- problem constants (fixed by setup_inputs) ----------------
#define NPTS   20000
#define NDST   5000
#define KNB    32

// FPS cluster config
#define FPS_B  8
#define FPS_T  256
#define PPT    5                              // pairs per thread (10 points)
#define PTS_PER_BLOCK (FPS_T * PPT * 2)       // 2560

// output layout (float32, concatenated in reference return order)
#define OFF_COORD 0
#define OFF_FEAT  15000
#define OFF_ESRC  655000
#define OFF_EDST  815000
#define OFF_DEG   975000
#define OFF_BATCH 980000

static __device__ float g_ssrc[NPTS];
static __device__ int   g_sel[NDST];
static __device__ int   g_nbr[NDST * KNB];
static __device__ int   g_deg[NDST];

typedef unsigned long long u64;

__device__ __forceinline__ u64 f2_add(u64 a, u64 b) {
    u64 r; asm("add.rn.f32x2 %0, %1, %2;" : "=l"(r) : "l"(a), "l"(b)); return r;
}
__device__ __forceinline__ u64 f2_mul(u64 a, u64 b) {
    u64 r; asm("mul.rn.f32x2 %0, %1, %2;" : "=l"(r) : "l"(a), "l"(b)); return r;
}
__device__ __forceinline__ u64 f2_pack(float lo, float hi) {
    u64 r; asm("mov.b64 %0, {%1, %2};" : "=l"(r) : "f"(lo), "f"(hi)); return r;
}
__device__ __forceinline__ float2 f2_unpack(u64 a) {
    float2 v; asm("mov.b64 {%0, %1}, %2;" : "=f"(v.x), "=f"(v.y) : "l"(a)); return v;
}
__device__ __forceinline__ u64 lds_rlx(uint32_t a) {
    u64 v; asm volatile("ld.relaxed.cluster.shared::cta.u64 %0, [%1];" : "=l"(v) : "r"(a));
    return v;
}
__device__ __forceinline__ void st_remote(uint32_t ra, u64 v) {
    asm volatile("st.relaxed.cluster.shared::cluster.u64 [%0], %1;" :: "r"(ra), "l"(v) : "memory");
}
__device__ __forceinline__ uint32_t mapa_rank(uint32_t la, uint32_t rank) {
    uint32_t ra;
    asm("mapa.shared::cluster.u32 %0, %1, %2;" : "=r"(ra) : "r"(la), "r"(rank));
    return ra;
}

// key layout: [63:51] iter tag (13b) | [50:19] value f32 bits | [14:0] 0x7fff - idx
__device__ __forceinline__ u64 make_key(unsigned iter, unsigned valbits, unsigned idx) {
    return ((u64)iter << 51) | ((u64)valbits << 19) | (u64)(0x7fffu - idx);
}

// reference-order squared distance: ((dx*dx + dy*dy) + dz*dz), no fma
__device__ __forceinline__ float d2_ref(float x, float y, float z,
                                        float cx, float cy, float cz) {
    float dx = __fsub_rn(x, cx), dy = __fsub_rn(y, cy), dz = __fsub_rn(z, cz);
    return __fadd_rn(__fadd_rn(__fmul_rn(dx, dx), __fmul_rn(dy, dy)),
                     __fmul_rn(dz, dz));
}

// ---------------- sum of squares per src point ----------------
__global__ void ssrc_kernel(const float* __restrict__ coord) {
    int j = blockIdx.x * blockDim.x + threadIdx.x;
    if (j < NPTS) {
        float x = coord[3 * j], y = coord[3 * j + 1], z = coord[3 * j + 2];
        g_ssrc[j] = __fadd_rn(__fadd_rn(__fmul_rn(x, x), __fmul_rn(y, y)),
                              __fmul_rn(z, z));
    }
}

// ---------------- farthest point sampling: 8-CTA cluster, DSMEM exchange ---
// Per-iter slot group per rank: [0]=key, [1..3]=tagged x/y/z bits of block winner.
__global__ __launch_bounds__(FPS_T, 1) __cluster_dims__(FPS_B, 1, 1)
void fps_kernel(const float* __restrict__ coord, float* __restrict__ out) {
    __shared__ float sXX[PTS_PER_BLOCK];
    __shared__ float sYY[PTS_PER_BLOCK];
    __shared__ float sZZ[PTS_PER_BLOCK];
    __shared__ u64 sSlot[2][FPS_B][4];     // double-buffered peer candidates
    __shared__ u64 sBest;                  // monotonic (iter tag in MSBs)

    const int t = threadIdx.x;
    const int b = blockIdx.x;              // == cluster rank (grid = 1 cluster)
    const int gbase = b * PTS_PER_BLOCK;

    float mind[2 * PPT];
    u64   zp[PPT];

    if (t < 2 * FPS_B * 4) ((u64*)sSlot)[t] = 0ull;   // tag 0 != any iter >= 1
    if (t == 0) sBest = 0ull;

    const float c0x = coord[0], c0y = coord[1], c0z = coord[2];
    float tmax = -1e30f;

#pragma unroll
    for (int k = 0; k < PPT; k++) {
        int p  = t + k * FPS_T;
        int i0 = gbase + 2 * p;
        int i1 = i0 + 1;
        float x0, y0, z0, x1, y1, z1, m0, m1;
        if (i0 < NPTS) {
            x0 = coord[3 * i0]; y0 = coord[3 * i0 + 1]; z0 = coord[3 * i0 + 2];
            m0 = d2_ref(x0, y0, z0, c0x, c0y, c0z);
        } else { x0 = y0 = z0 = 1e18f; m0 = -1.0f; }
        if (i1 < NPTS) {
            x1 = coord[3 * i1]; y1 = coord[3 * i1 + 1]; z1 = coord[3 * i1 + 2];
            m1 = d2_ref(x1, y1, z1, c0x, c0y, c0z);
        } else { x1 = y1 = z1 = 1e18f; m1 = -1.0f; }
        sXX[2 * p] = x0; sXX[2 * p + 1] = x1;
        sYY[2 * p] = y0; sYY[2 * p + 1] = y1;
        sZZ[2 * p] = z0; sZZ[2 * p + 1] = z1;
        zp[k] = f2_pack(z0, z1);
        mind[2 * k] = m0; mind[2 * k + 1] = m1;
        tmax = fmaxf(tmax, fmaxf(m0, m1));
    }

    // per-thread first-index of the max
    int bidx = 0x7FFF;
#pragma unroll
    for (int k = 0; k < PPT; k++) {
        int g = gbase + 2 * (t + k * FPS_T);
        if (mind[2 * k] == tmax && g < bidx)           bidx = g;
        if (mind[2 * k + 1] == tmax && (g + 1) < bidx) bidx = g + 1;
    }

    if (b == 0 && t == 0) {
        g_sel[0] = 0;
        out[OFF_COORD + 0] = c0x; out[OFF_COORD + 1] = c0y; out[OFF_COORD + 2] = c0z;
    }
    __syncthreads();
    // all CTAs' slot-zeroing must be visible before any remote publish lands
    asm volatile("barrier.cluster.arrive.aligned;" ::: "memory");
    asm volatile("barrier.cluster.wait.aligned;" ::: "memory");

    const uint32_t slotBase = (uint32_t)__cvta_generic_to_shared(&sSlot[0][0][0]);

    for (int i = 1; i < NDST; i++) {
        // --- local reduce: per-warp redux, per-block atomicMax (tag-dominant) ---
        unsigned vb = __float_as_uint(fmaxf(tmax, 0.0f));
        unsigned wm = __reduce_max_sync(0xffffffffu, vb);
        unsigned ci = (vb == wm) ? (unsigned)bidx : 0x7fffu;
        unsigned im = __reduce_min_sync(0xffffffffu, ci);
        if ((t & 31) == 0) atomicMax(&sBest, make_key((unsigned)i, wm, im));
        __syncthreads();

        const uint32_t par = (uint32_t)(i & 1);
        // --- publish key + winner coords into every CTA's slot group [par][b] ---
        if (t < 4 * FPS_B) {
            const int r = t >> 2, s = t & 3;
            u64 kk = sBest;
            u64 v;
            if (s == 0) v = kk;
            else {
                int li = (0x7FFF - (int)(kk & 0x7FFFu)) - gbase;   // block-local winner
                float c = (s == 1) ? sXX[li] : (s == 2) ? sYY[li] : sZZ[li];
                v = ((u64)(unsigned)i << 32) | (u64)__float_as_uint(c);
            }
            uint32_t la = slotBase + ((par * FPS_B + (uint32_t)b) * 4u + (uint32_t)s) * 8u;
            st_remote(mapa_rank(la, (uint32_t)r), v);
        }

        // --- poll all 8 keys in parallel; retry until every tag matches ---
        const uint32_t gb = slotBase + par * FPS_B * 4u * 8u;
        u64 kk[FPS_B];
        bool ok;
        do {
#pragma unroll
            for (int r = 0; r < FPS_B; r++) kk[r] = lds_rlx(gb + (uint32_t)r * 32u);
            ok = true;
#pragma unroll
            for (int r = 0; r < FPS_B; r++) ok &= ((unsigned)(kk[r] >> 51) == (unsigned)i);
        } while (!ok);

        u64 best = kk[0];
#pragma unroll
        for (int r = 1; r < FPS_B; r++) best = (kk[r] > best) ? kk[r] : best;
        const int sel = 0x7FFF - (int)(best & 0x7FFFu);
        const uint32_t w = (uint32_t)(sel / PTS_PER_BLOCK);   // owning rank

        // --- poll winner's 3 coord slots (issued with its key; arrive together) ---
        const uint32_t cb = gb + w * 32u;
        u64 c1, c2, c3;
        do {
            c1 = lds_rlx(cb + 8u); c2 = lds_rlx(cb + 16u); c3 = lds_rlx(cb + 24u);
            ok = ((unsigned)(c1 >> 32) == (unsigned)i) &
                 ((unsigned)(c2 >> 32) == (unsigned)i) &
                 ((unsigned)(c3 >> 32) == (unsigned)i);
        } while (!ok);
        const float cx = __uint_as_float((unsigned)c1);
        const float cy = __uint_as_float((unsigned)c2);
        const float cz = __uint_as_float((unsigned)c3);

        if (b == 0 && t == 0) {
            g_sel[i] = sel;
            out[OFF_COORD + 3 * i]     = cx;
            out[OFF_COORD + 3 * i + 1] = cy;
            out[OFF_COORD + 3 * i + 2] = cz;
        }

        // --- update min distances (packed f32x2; exact per-element rounding) ---
        const u64 ncx = f2_pack(-cx, -cx);
        const u64 ncy = f2_pack(-cy, -cy);
        const u64 ncz = f2_pack(-cz, -cz);
        float tA = -1e30f, tB = -1e30f;
#pragma unroll
        for (int k = 0; k < PPT; k++) {
            int p = t + k * FPS_T;
            u64 xx = *reinterpret_cast<const u64*>(&sXX[2 * p]);
            u64 yy = *reinterpret_cast<const u64*>(&sYY[2 * p]);
            u64 dx = f2_add(xx, ncx);
            u64 dy = f2_add(yy, ncy);
            u64 dz = f2_add(zp[k], ncz);
            u64 d2 = f2_add(f2_add(f2_mul(dx, dx), f2_mul(dy, dy)), f2_mul(dz, dz));
            float2 d = f2_unpack(d2);
            mind[2 * k]     = fminf(mind[2 * k], d.x);
            mind[2 * k + 1] = fminf(mind[2 * k + 1], d.y);
            tA = fmaxf(tA, mind[2 * k]);
            tB = fmaxf(tB, mind[2 * k + 1]);
        }
        tmax = fmaxf(tA, tB);

        // per-thread first-index of new max
        bidx = 0x7FFF;
#pragma unroll
        for (int k = 0; k < PPT; k++) {
            int g = gbase + 2 * (t + k * FPS_T);
            if (mind[2 * k] == tmax && g < bidx)           bidx = g;
            if (mind[2 * k + 1] == tmax && (g + 1) < bidx) bidx = g + 1;
        }
    }

    // keep cluster resident until all remote traffic has been consumed
    asm volatile("barrier.cluster.arrive.aligned;" ::: "memory");
    asm volatile("barrier.cluster.wait.aligned;" ::: "memory");
}

// ---------------- ball query: one warp per dst, ordered append -------------
__global__ void ball_kernel(const float* __restrict__ coord,
                            const int* __restrict__ batch,
                            float* __restrict__ out) {
    __shared__ int sN[4][KNB];
    const int warp = threadIdx.x >> 5;
    const int lane = threadIdx.x & 31;
    const int d = blockIdx.x * 4 + warp;
    if (d >= NDST) return;

    const float R2 = (float)(0.08 * 0.08);
    const int sel = g_sel[d];
    const float cx = coord[3 * sel], cy = coord[3 * sel + 1], cz = coord[3 * sel + 2];
    const float sd = g_ssrc[sel];

    int cnt = 0;
    for (int j0 = 0; j0 < NPTS; j0 += 32) {
        const int j = j0 + lane;   // NPTS % 32 == 0, no tail
        float xj = coord[3 * j], yj = coord[3 * j + 1], zj = coord[3 * j + 2];
        float sj = g_ssrc[j];
        float dot = __fmaf_rn(cz, zj, __fmaf_rn(cy, yj, __fmul_rn(cx, xj)));
        float d2 = __fsub_rn(__fadd_rn(sd, sj), __fmul_rn(2.0f, dot));
        bool w = (d2 <= R2);
        unsigned bal = __ballot_sync(0xffffffffu, w);
        int pos = cnt + __popc(bal & ((1u << lane) - 1u));
        if (w && pos < KNB) sN[warp][pos] = j;
        cnt += __popc(bal);
        if (cnt >= KNB) break;
    }
    __syncwarp();

    const int deg = min(cnt, KNB);
    const int base = d * KNB;
    int nb = (lane < deg) ? sN[warp][lane] : -1;
    g_nbr[base + lane] = nb;
    out[OFF_ESRC + base + lane] = (float)nb;
    out[OFF_EDST + base + lane] = (lane < deg) ? (float)d : -1.0f;
    if (lane == 0) {
        g_deg[d] = deg;
        out[OFF_DEG + d] = (float)deg;
        out[OFF_BATCH + d] = (float)batch[sel];
    }
}

// ---------------- feature scatter-mean: one block (128 thr) per dst --------
__global__ void feat_kernel(const float* __restrict__ feat,
                            float* __restrict__ out) {
    __shared__ int sNbr[KNB];
    __shared__ int sDeg;
    const int d = blockIdx.x;
    const int tid = threadIdx.x;
    if (tid < KNB) sNbr[tid] = g_nbr[d * KNB + tid];
    if (tid == 0)  sDeg = g_deg[d];
    __syncthreads();
    const int dg = sDeg;
    float acc = 0.0f;
    for (int k = 0; k < dg; k++)
        acc = __fadd_rn(acc, feat[(size_t)sNbr[k] * 128 + tid]);
    out[OFF_FEAT + (size_t)d * 128 + tid] = acc / (float)max(dg, 1);
}

// ---------------- launch ----------------
extern "C" void kernel_launch(void* const* d_in, const int* in_sizes, int n_in,
                              void* d_out, int out_size) {
    const float* coord = (const float*)d_in[0];
    const float* feat  = (const float*)d_in[1];
    const int*   batch = (const int*)d_in[2];
    float* out = (float*)d_out;

    ssrc_kernel<<<(NPTS + 255) / 256, 256>>>(coord);
    fps_kernel<<<FPS_B, FPS_T>>>(coord, out);
    ball_kernel<<<(NDST + 3) / 4, 128>>>(coord, batch, out);
    feat_kernel<<<NDST, 128>>>(feat, out);
}

// round 7
// speedup vs baseline: 3.0639x; 1.3236x over previous
#include <cuda_runtime.h>
#include <cuda_bf16.h>
#include <cstdint>

// ---------------- problem constants (fixed by setup_inputs) ----------------
#define NPTS   20000
#define NDST   5000
#define KNB    32

// FPS cluster config
#define FPS_B  8
#define FPS_T  256
#define PPT    5                              // pairs per thread (10 points)
#define PTS_PER_BLOCK (FPS_T * PPT * 2)       // 2560
#define NWARP  8                              // warps per CTA
#define NSLOT  (FPS_B * NWARP)                // 64 warp slots cluster-wide

// output layout (float32, concatenated in reference return order)
#define OFF_COORD 0
#define OFF_FEAT  15000
#define OFF_ESRC  655000
#define OFF_EDST  815000
#define OFF_DEG   975000
#define OFF_BATCH 980000

static __device__ float g_ssrc[NPTS];
static __device__ int   g_sel[NDST];
static __device__ int   g_nbr[NDST * KNB];
static __device__ int   g_deg[NDST];

typedef unsigned long long u64;

__device__ __forceinline__ u64 f2_add(u64 a, u64 b) {
    u64 r; asm("add.rn.f32x2 %0, %1, %2;" : "=l"(r) : "l"(a), "l"(b)); return r;
}
__device__ __forceinline__ u64 f2_mul(u64 a, u64 b) {
    u64 r; asm("mul.rn.f32x2 %0, %1, %2;" : "=l"(r) : "l"(a), "l"(b)); return r;
}
__device__ __forceinline__ u64 f2_pack(float lo, float hi) {
    u64 r; asm("mov.b64 %0, {%1, %2};" : "=l"(r) : "f"(lo), "f"(hi)); return r;
}
__device__ __forceinline__ float2 f2_unpack(u64 a) {
    float2 v; asm("mov.b64 {%0, %1}, %2;" : "=f"(v.x), "=f"(v.y) : "l"(a)); return v;
}
__device__ __forceinline__ u64 lds_rlx(uint32_t a) {
    u64 v; asm volatile("ld.relaxed.cluster.shared::cta.u64 %0, [%1];" : "=l"(v) : "r"(a));
    return v;
}
__device__ __forceinline__ void st_remote(uint32_t ra, u64 v) {
    asm volatile("st.relaxed.cluster.shared::cluster.u64 [%0], %1;" :: "r"(ra), "l"(v) : "memory");
}
__device__ __forceinline__ uint32_t mapa_rank(uint32_t la, uint32_t rank) {
    uint32_t ra;
    asm("mapa.shared::cluster.u32 %0, %1, %2;" : "=r"(ra) : "r"(la), "r"(rank));
    return ra;
}

// reference-order squared distance: ((dx*dx + dy*dy) + dz*dz), no fma
__device__ __forceinline__ float d2_ref(float x, float y, float z,
                                        float cx, float cy, float cz) {
    float dx = __fsub_rn(x, cx), dy = __fsub_rn(y, cy), dz = __fsub_rn(z, cz);
    return __fadd_rn(__fadd_rn(__fmul_rn(dx, dx), __fmul_rn(dy, dy)),
                     __fmul_rn(dz, dz));
}

// ---------------- sum of squares per src point ----------------
__global__ void ssrc_kernel(const float* __restrict__ coord) {
    int j = blockIdx.x * blockDim.x + threadIdx.x;
    if (j < NPTS) {
        float x = coord[3 * j], y = coord[3 * j + 1], z = coord[3 * j + 2];
        g_ssrc[j] = __fadd_rn(__fadd_rn(__fmul_rn(x, x), __fmul_rn(y, y)),
                              __fmul_rn(z, z));
    }
}

// ---------------- FPS: 8-CTA cluster, warp-synchronous all-to-all ----------
// Key layout: [59:47] iter tag | [46:15] value f32 bits | [14:0] 0x7fff - idx
// Coord slot: [63:32] iter tag | [31:0] f32 bits
// Slot group (32B) per (parity, cta, warp): [key, x, y, z]
__global__ __launch_bounds__(FPS_T, 1) __cluster_dims__(FPS_B, 1, 1)
void fps_kernel(const float* __restrict__ coord, float* __restrict__ out) {
    __shared__ float sXX[PTS_PER_BLOCK];
    __shared__ float sYY[PTS_PER_BLOCK];
    __shared__ float sZZ[PTS_PER_BLOCK];
    __shared__ u64 sSlot[2][NSLOT][4];

    const int t = threadIdx.x;
    const int b = blockIdx.x;              // cluster rank (grid = 1 cluster)
    const int warp = t >> 5;
    const int lane = t & 31;
    const int gbase = b * PTS_PER_BLOCK;

    float mind[2 * PPT];
    u64   zp[PPT];

    // zero slots (tag 0 never matches iter >= 1)
    if (t < 256) { ((u64*)sSlot)[t] = 0ull; ((u64*)sSlot)[t + 256] = 0ull; }

    const float c0x = coord[0], c0y = coord[1], c0z = coord[2];
    float tmax = -1e30f;

#pragma unroll
    for (int k = 0; k < PPT; k++) {
        int p  = t + k * FPS_T;
        int i0 = gbase + 2 * p;
        int i1 = i0 + 1;
        float x0, y0, z0, x1, y1, z1, m0, m1;
        if (i0 < NPTS) {
            x0 = coord[3 * i0]; y0 = coord[3 * i0 + 1]; z0 = coord[3 * i0 + 2];
            m0 = d2_ref(x0, y0, z0, c0x, c0y, c0z);
        } else { x0 = y0 = z0 = 1e18f; m0 = -1.0f; }
        if (i1 < NPTS) {
            x1 = coord[3 * i1]; y1 = coord[3 * i1 + 1]; z1 = coord[3 * i1 + 2];
            m1 = d2_ref(x1, y1, z1, c0x, c0y, c0z);
        } else { x1 = y1 = z1 = 1e18f; m1 = -1.0f; }
        sXX[2 * p] = x0; sXX[2 * p + 1] = x1;
        sYY[2 * p] = y0; sYY[2 * p + 1] = y1;
        sZZ[2 * p] = z0; sZZ[2 * p + 1] = z1;
        zp[k] = f2_pack(z0, z1);
        mind[2 * k] = m0; mind[2 * k + 1] = m1;
        tmax = fmaxf(tmax, fmaxf(m0, m1));
    }

    // per-thread first-index of the max
    int bidx = 0x7FFF;
#pragma unroll
    for (int k = 0; k < PPT; k++) {
        int g = gbase + 2 * (t + k * FPS_T);
        if (mind[2 * k] == tmax && g < bidx)           bidx = g;
        if (mind[2 * k + 1] == tmax && (g + 1) < bidx) bidx = g + 1;
    }

    if (b == 0 && t == 0) {
        g_sel[0] = 0;
        out[OFF_COORD + 0] = c0x; out[OFF_COORD + 1] = c0y; out[OFF_COORD + 2] = c0z;
    }
    __syncthreads();
    // all CTAs' slot-zeroing + smem tiles visible before any remote publish
    asm volatile("barrier.cluster.arrive.aligned;" ::: "memory");
    asm volatile("barrier.cluster.wait.aligned;" ::: "memory");

    const uint32_t slotBase = (uint32_t)__cvta_generic_to_shared(&sSlot[0][0][0]);
    const int sid = b * NWARP + warp;      // this warp's cluster-wide slot id
    const uint32_t myOff = (uint32_t)sid * 32u;
    const int peer = lane >> 2, s = lane & 3;   // publish fan-out mapping

    for (int i = 1; i < NDST; i++) {
        // --- warp-level candidate (val, first-idx) via 32-bit redux ---
        unsigned vb = __float_as_uint(fmaxf(tmax, 0.0f));
        unsigned wm = __reduce_max_sync(0xffffffffu, vb);
        unsigned inv = (vb == wm) ? (unsigned)(0x7FFF - bidx) : 0u;
        unsigned wi = __reduce_max_sync(0xffffffffu, inv);
        const int widx = 0x7FFF - (int)wi;      // warp winner, global idx
        const int li = widx - gbase;            // local (this warp owns it)

        const uint32_t par = (uint32_t)(i & 1);
        const uint32_t parOff = par * (NSLOT * 32u);

        // --- publish key + winner coords to every CTA (1 store per lane) ---
        {
            u64 v;
            if (s == 0) {
                v = ((u64)(unsigned)i << 47) | ((u64)wm << 15) | (u64)wi;
            } else {
                float c = (s == 1) ? sXX[li] : (s == 2) ? sYY[li] : sZZ[li];
                v = ((u64)(unsigned)i << 32) | (u64)__float_as_uint(c);
            }
            uint32_t la = slotBase + parOff + myOff + (uint32_t)s * 8u;
            st_remote(mapa_rank(la, (uint32_t)peer), v);
        }

        // --- poll all 64 keys (2 per lane), ballot until complete ---
        const uint32_t gbuf = slotBase + parOff;
        const uint32_t a0 = gbuf + (uint32_t)lane * 32u;
        const uint32_t a1 = a0 + 32u * 32u;
        u64 k0, k1;
        for (;;) {
            k0 = lds_rlx(a0); k1 = lds_rlx(a1);
            bool o = ((unsigned)(k0 >> 47) == (unsigned)i) &
                     ((unsigned)(k1 >> 47) == (unsigned)i);
            if (__all_sync(0xffffffffu, o)) break;
        }
        u64 k = (k0 > k1) ? k0 : k1;
        unsigned v32 = (unsigned)(k >> 15);        // value bits
        unsigned i15 = (unsigned)(k & 0x7FFFu);    // inv idx
        unsigned vmax = __reduce_max_sync(0xffffffffu, v32);
        unsigned imax = __reduce_max_sync(0xffffffffu, (v32 == vmax) ? i15 : 0u);
        const int sel = 0x7FFF - (int)imax;

        // --- winner's coord slots (arrive with its key; tag-checked) ---
        const int wc = sel / PTS_PER_BLOCK;
        const int lp = (sel - wc * PTS_PER_BLOCK) >> 1;
        const int ww = (lp & 255) >> 5;
        const uint32_t cb = gbuf + (uint32_t)(wc * NWARP + ww) * 32u;
        u64 c1, c2, c3;
        for (;;) {
            c1 = lds_rlx(cb + 8u); c2 = lds_rlx(cb + 16u); c3 = lds_rlx(cb + 24u);
            bool o = ((unsigned)(c1 >> 32) == (unsigned)i) &
                     ((unsigned)(c2 >> 32) == (unsigned)i) &
                     ((unsigned)(c3 >> 32) == (unsigned)i);
            if (o) break;
        }
        const float cx = __uint_as_float((unsigned)c1);
        const float cy = __uint_as_float((unsigned)c2);
        const float cz = __uint_as_float((unsigned)c3);

        if (b == 0 && t == 0) {
            g_sel[i] = sel;
            out[OFF_COORD + 3 * i]     = cx;
            out[OFF_COORD + 3 * i + 1] = cy;
            out[OFF_COORD + 3 * i + 2] = cz;
        }

        // --- update min distances (packed f32x2; exact per-element rounding) ---
        const u64 ncx = f2_pack(-cx, -cx);
        const u64 ncy = f2_pack(-cy, -cy);
        const u64 ncz = f2_pack(-cz, -cz);
        float tA = -1e30f, tB = -1e30f;
#pragma unroll
        for (int kk = 0; kk < PPT; kk++) {
            int p = t + kk * FPS_T;
            u64 xx = *reinterpret_cast<const u64*>(&sXX[2 * p]);
            u64 yy = *reinterpret_cast<const u64*>(&sYY[2 * p]);
            u64 dx = f2_add(xx, ncx);
            u64 dy = f2_add(yy, ncy);
            u64 dz = f2_add(zp[kk], ncz);
            u64 d2 = f2_add(f2_add(f2_mul(dx, dx), f2_mul(dy, dy)), f2_mul(dz, dz));
            float2 d = f2_unpack(d2);
            mind[2 * kk]     = fminf(mind[2 * kk], d.x);
            mind[2 * kk + 1] = fminf(mind[2 * kk + 1], d.y);
            tA = fmaxf(tA, mind[2 * kk]);
            tB = fmaxf(tB, mind[2 * kk + 1]);
        }
        tmax = fmaxf(tA, tB);

        // per-thread first-index of new max
        bidx = 0x7FFF;
#pragma unroll
        for (int kk = 0; kk < PPT; kk++) {
            int g = gbase + 2 * (t + kk * FPS_T);
            if (mind[2 * kk] == tmax && g < bidx)           bidx = g;
            if (mind[2 * kk + 1] == tmax && (g + 1) < bidx) bidx = g + 1;
        }
    }

    // keep cluster resident until all remote traffic has been consumed
    asm volatile("barrier.cluster.arrive.aligned;" ::: "memory");
    asm volatile("barrier.cluster.wait.aligned;" ::: "memory");
}

// ---------------- ball query: one warp per dst, ordered append -------------
__global__ void ball_kernel(const float* __restrict__ coord,
                            const int* __restrict__ batch,
                            float* __restrict__ out) {
    __shared__ int sN[4][KNB];
    const int warp = threadIdx.x >> 5;
    const int lane = threadIdx.x & 31;
    const int d = blockIdx.x * 4 + warp;
    if (d >= NDST) return;

    const float R2 = (float)(0.08 * 0.08);
    const int sel = g_sel[d];
    const float cx = coord[3 * sel], cy = coord[3 * sel + 1], cz = coord[3 * sel + 2];
    const float sd = g_ssrc[sel];

    int cnt = 0;
    for (int j0 = 0; j0 < NPTS; j0 += 32) {
        const int j = j0 + lane;   // NPTS % 32 == 0, no tail
        float xj = coord[3 * j], yj = coord[3 * j + 1], zj = coord[3 * j + 2];
        float sj = g_ssrc[j];
        float dot = __fmaf_rn(cz, zj, __fmaf_rn(cy, yj, __fmul_rn(cx, xj)));
        float d2 = __fsub_rn(__fadd_rn(sd, sj), __fmul_rn(2.0f, dot));
        bool w = (d2 <= R2);
        unsigned bal = __ballot_sync(0xffffffffu, w);
        int pos = cnt + __popc(bal & ((1u << lane) - 1u));
        if (w && pos < KNB) sN[warp][pos] = j;
        cnt += __popc(bal);
        if (cnt >= KNB) break;
    }
    __syncwarp();

    const int deg = min(cnt, KNB);
    const int base = d * KNB;
    int nb = (lane < deg) ? sN[warp][lane] : -1;
    g_nbr[base + lane] = nb;
    out[OFF_ESRC + base + lane] = (float)nb;
    out[OFF_EDST + base + lane] = (lane < deg) ? (float)d : -1.0f;
    if (lane == 0) {
        g_deg[d] = deg;
        out[OFF_DEG + d] = (float)deg;
        out[OFF_BATCH + d] = (float)batch[sel];
    }
}

// ---------------- feature scatter-mean: one block (128 thr) per dst --------
__global__ void feat_kernel(const float* __restrict__ feat,
                            float* __restrict__ out) {
    __shared__ int sNbr[KNB];
    __shared__ int sDeg;
    const int d = blockIdx.x;
    const int tid = threadIdx.x;
    if (tid < KNB) sNbr[tid] = g_nbr[d * KNB + tid];
    if (tid == 0)  sDeg = g_deg[d];
    __syncthreads();
    const int dg = sDeg;
    float acc = 0.0f;
    for (int k = 0; k < dg; k++)
        acc = __fadd_rn(acc, feat[(size_t)sNbr[k] * 128 + tid]);
    out[OFF_FEAT + (size_t)d * 128 + tid] = acc / (float)max(dg, 1);
}

// ---------------- launch ----------------
extern "C" void kernel_launch(void* const* d_in, const int* in_sizes, int n_in,
                              void* d_out, int out_size) {
    const float* coord = (const float*)d_in[0];
    const float* feat  = (const float*)d_in[1];
    const int*   batch = (const int*)d_in[2];
    float* out = (float*)d_out;

    ssrc_kernel<<<(NPTS + 255) / 256, 256>>>(coord);
    fps_kernel<<<FPS_B, FPS_T>>>(coord, out);
    ball_kernel<<<(NDST + 3) / 4, 128>>>(coord, batch, out);
    feat_kernel<<<NDST, 128>>>(feat, out);
}